// round 13
// baseline (speedup 1.0000x reference)
#include <cuda_runtime.h>
#include <cstdint>
#include <math.h>

constexpr int B_ = 64;
constexpr int N_ = 1024;
constexpr int D_ = 512;
constexpr int K_ = 64;
constexpr int C_ = K_ + N_;                      // 1088
constexpr long OUT_ELEMS = (long)B_ * K_ * D_;
constexpr long DOTS_OFF  = OUT_ELEMS;

#define TEMP_INV (1.0f / 0.07f)

__device__ float g_shat[K_ * D_];                // tf32-rounded normalized slots
__device__ float g_S[K_ * K_];                   // exact slot-slot cosines
__device__ float g_attn[(long)B_ * K_ * C_];     // tf32-rounded attn weights
__device__ int   g_cnt[B_];                      // per-batch CTA completion counters

__device__ __forceinline__ float to_tf32(float x) {
    asm("cvt.rna.tf32.f32 %0, %1;" : "=f"(x) : "f"(x));
    return x;
}
__device__ __forceinline__ uint32_t smem_u32(const void* p) {
    uint32_t a;
    asm("{ .reg .u64 t; cvta.to.shared.u64 t, %1; cvt.u32.u64 %0, t; }" : "=r"(a) : "l"(p));
    return a;
}
__device__ __forceinline__ void cp16(uint32_t dst, const void* src) {
    asm volatile("cp.async.cg.shared.global [%0], [%1], 16;" :: "r"(dst), "l"(src));
}
__device__ __forceinline__ void cp_commit() {
    asm volatile("cp.async.commit_group;" ::: "memory");
}
__device__ __forceinline__ void ldsm4(uint32_t* r, uint32_t addr) {
    asm volatile("ldmatrix.sync.aligned.m8n8.x4.shared.b16 {%0,%1,%2,%3}, [%4];"
        : "=r"(r[0]), "=r"(r[1]), "=r"(r[2]), "=r"(r[3]) : "r"(addr));
}
__device__ __forceinline__ void mma8(float* d, const uint32_t* a, const uint32_t* b) {
    asm volatile("mma.sync.aligned.m16n8k8.row.col.f32.tf32.tf32.f32 "
        "{%0,%1,%2,%3}, {%4,%5,%6,%7}, {%8,%9}, {%0,%1,%2,%3};"
        : "+f"(d[0]), "+f"(d[1]), "+f"(d[2]), "+f"(d[3])
        : "r"(a[0]), "r"(a[1]), "r"(a[2]), "r"(a[3]), "r"(b[0]), "r"(b[1]));
}

// ---------------------------------------------------------------------------
// K1: slot prep (dots, norms, S, shat) + counter reset.
// ---------------------------------------------------------------------------
__global__ void k_prep(const float* __restrict__ slot) {
    int i = blockIdx.x, j = threadIdx.x;   // 64 threads
    if (j == 0) g_cnt[i] = 0;
    const float4* a = (const float4*)(slot + i * D_);
    const float4* b = (const float4*)(slot + j * D_);
    float dot = 0.f, nj = 0.f;
#pragma unroll 8
    for (int d = 0; d < D_ / 4; d++) {
        float4 x = a[d], y = b[d];
        dot += x.x * y.x + x.y * y.y + x.z * y.z + x.w * y.w;
        nj  += y.x * y.x + y.y * y.y + y.z * y.z + y.w * y.w;
    }
    __shared__ float n[64];
    n[j] = nj;
    __syncthreads();
    float inv_j = 1.f / fmaxf(sqrtf(nj),   1e-12f);
    float inv_i = 1.f / fmaxf(sqrtf(n[i]), 1e-12f);
    g_S[i * K_ + j] = dot * inv_i * inv_j;
#pragma unroll
    for (int q = 0; q < 8; q++) {
        int d = j + 64 * q;
        g_shat[i * D_ + d] = to_tf32(slot[i * D_ + d] * inv_i);
    }
}

// ---------------------------------------------------------------------------
// K2: dots key-part GEMM (proven R11 core) + FUSED per-batch softmax:
// the last of the 4 CTAs of batch b runs the full 64-row softmax, reading
// the just-written dots from L2 (__ldcg), stashing exp in freed pipe smem.
// ---------------------------------------------------------------------------
constexpr int SD_KINV = 0;                        // 256 floats
constexpr int SD_PIPE = 256;
constexpr int SD_ASZ  = 256 * 20;                 // A stage (floats)
constexpr int SD_BSZ  = 64 * 20;                  // B stage
constexpr int SD_STG  = SD_ASZ + SD_BSZ;          // 6400
constexpr int SD_TOT  = SD_PIPE + 3 * SD_STG;     // 19456 floats = 77824 B

__global__ __launch_bounds__(256, 2) void k_dots(const float* __restrict__ key,
                                                 float* __restrict__ dout) {
    extern __shared__ float smf[];
    __shared__ int lastflag;
    const uint32_t sb = smem_u32(smf);
    const int t = threadIdx.x, wid = t >> 5, l = t & 31;
    const int b = blockIdx.y, n0blk = blockIdx.x * 256;
    const float* keyb = key + (long)b * N_ * D_;
    const int m0 = wid * 32;

    const int laneA = ((((l >> 3) & 1) * 8 + (l & 7)) * 20) + (l >> 4) * 4;
    const int laneB = (((l >> 4) * 8 + (l & 7)) * 20) + ((l >> 3) & 1) * 4;

    float c[2][8][4];
#pragma unroll
    for (int i = 0; i < 2; i++)
#pragma unroll
        for (int j = 0; j < 8; j++)
#pragma unroll
            for (int k = 0; k < 4; k++) c[i][j][k] = 0.f;

    float ss = 0.f;

    auto issue = [&](int jc) {
        int s = jc % 3;
        uint32_t ab = sb + (SD_PIPE + s * SD_STG) * 4;
        uint32_t bb = ab + SD_ASZ * 4;
        const float* gA = keyb + (long)n0blk * D_ + jc * 16;
#pragma unroll
        for (int q = 0; q < 4; q++) {
            int idx = t + 256 * q, row = idx >> 2, f = idx & 3;
            cp16(ab + (row * 20 + f * 4) * 4, gA + (long)row * D_ + f * 4);
        }
        {
            int row = t >> 2, f = t & 3;
            cp16(bb + (row * 20 + f * 4) * 4, g_shat + row * D_ + jc * 16 + f * 4);
        }
        cp_commit();
    };

    issue(0);
    issue(1);

    for (int jc = 0; jc < 32; jc++) {
        if (jc + 1 < 32) asm volatile("cp.async.wait_group 1;" ::: "memory");
        else             asm volatile("cp.async.wait_group 0;" ::: "memory");
        __syncthreads();
        if (jc + 2 < 32) issue(jc + 2);
        const int s = jc % 3;
        const float* As = smf + SD_PIPE + s * SD_STG;
        uint32_t a4 = sb + (SD_PIPE + s * SD_STG) * 4;
        uint32_t b4 = a4 + SD_ASZ * 4;
#pragma unroll
        for (int f = 0; f < 4; f++) {
            float4 v = *(const float4*)(As + t * 20 + f * 4);
            ss += v.x * v.x + v.y * v.y + v.z * v.z + v.w * v.w;
        }
#pragma unroll
        for (int k8 = 0; k8 < 16; k8 += 8) {
            uint32_t a[2][4], bf[4][4];
            ldsm4(a[0], a4 + ((m0)      * 20 + k8 + laneA) * 4);
            ldsm4(a[1], a4 + ((m0 + 16) * 20 + k8 + laneA) * 4);
#pragma unroll
            for (int p = 0; p < 4; p++)
                ldsm4(bf[p], b4 + ((16 * p) * 20 + k8 + laneB) * 4);
#pragma unroll
            for (int mb = 0; mb < 2; mb++)
#pragma unroll
                for (int p = 0; p < 4; p++) {
                    mma8(c[mb][2 * p],     a[mb], &bf[p][0]);
                    mma8(c[mb][2 * p + 1], a[mb], &bf[p][2]);
                }
        }
    }

    smf[SD_KINV + t] = 1.f / fmaxf(sqrtf(ss), 1e-12f);
    __syncthreads();

    // epilogue: direct global store of dots[slot][key] with kinv scaling
    {
        int g = l >> 2, tq = l & 3;
        float* base = dout + DOTS_OFF + (long)b * K_ * C_ + K_;
#pragma unroll
        for (int mb = 0; mb < 2; mb++) {
            int kl0 = m0 + 16 * mb + g, kl1 = kl0 + 8;
            float kv0 = smf[SD_KINV + kl0], kv1 = smf[SD_KINV + kl1];
            long key0 = n0blk + kl0, key1 = n0blk + kl1;
#pragma unroll
            for (int nb = 0; nb < 8; nb++) {
                int s0 = nb * 8 + 2 * tq;
                base[(long)s0 * C_ + key0]       = c[mb][nb][0] * kv0;
                base[(long)(s0 + 1) * C_ + key0] = c[mb][nb][1] * kv0;
                base[(long)s0 * C_ + key1]       = c[mb][nb][2] * kv1;
                base[(long)(s0 + 1) * C_ + key1] = c[mb][nb][3] * kv1;
            }
        }
    }

    // ---- fused softmax: last CTA of this batch handles all 64 rows ----
    __threadfence();
    if (t == 0) lastflag = (atomicAdd(&g_cnt[b], 1) == 3);
    __syncthreads();
    if (!lastflag) return;

    // per-warp stash in freed pipeline smem: 1088 floats each
    float* stash = smf + 256 + wid * 1152;
#pragma unroll 1
    for (int rr = 0; rr < 8; rr++) {
        int i = wid * 8 + rr;                       // row (slot) index
        float* drow = dout + DOTS_OFF + (long)b * K_ * C_ + (long)i * C_;
        float s0 = g_S[i * K_ + l], s1 = g_S[i * K_ + l + 32];

        // pass 1: max
        float m = -1e30f;
        if (l < i)      m = s0;
        if (l + 32 < i) m = fmaxf(m, s1);
#pragma unroll 4
        for (int r = 0; r < 32; r++)
            m = fmaxf(m, __ldcg(drow + K_ + l + 32 * r));
#pragma unroll
        for (int o = 16; o; o >>= 1) m = fmaxf(m, __shfl_xor_sync(0xffffffffu, m, o));

        // pass 2: exp -> stash, sum
        float e0 = (l < i)      ? __expf((s0 - m) * TEMP_INV) : 0.f;
        float e1 = (l + 32 < i) ? __expf((s1 - m) * TEMP_INV) : 0.f;
        stash[l] = e0; stash[l + 32] = e1;
        float sum = e0 + e1;
#pragma unroll 4
        for (int r = 0; r < 32; r++) {
            float x = __expf((__ldcg(drow + K_ + l + 32 * r) - m) * TEMP_INV);
            stash[K_ + l + 32 * r] = x;
            sum += x;
        }
#pragma unroll
        for (int o = 16; o; o >>= 1) sum += __shfl_xor_sync(0xffffffffu, sum, o);
        float inv = 1.f / (sum * (1.f + 1e-7f));

        // pass 3: write attn (tf32) + dots slot part (raw S)
        float* at = g_attn + ((long)b * K_ + i) * C_;
        at[l]      = to_tf32(stash[l] * inv);
        at[l + 32] = to_tf32(stash[l + 32] * inv);
#pragma unroll 4
        for (int r = 0; r < 32; r++)
            at[K_ + l + 32 * r] = to_tf32(stash[K_ + l + 32 * r] * inv);
        drow[l] = s0;
        drow[l + 32] = s1;
    }
}

// ---------------------------------------------------------------------------
// K3: out = attn_n @ [slots; key_b].  (unchanged proven R12 core)
// ---------------------------------------------------------------------------
constexpr int SO_ASZ = 64 * 20;                   // 1280 floats per stage
constexpr int SO_BSZ = 16 * 136;                  // 2176
constexpr int SO_STG = SO_ASZ + SO_BSZ;           // 3456
constexpr int SO_TOT = 3 * SO_STG;                // 10368 floats = 41472 B

__global__ __launch_bounds__(256) void k_out(const float* __restrict__ slot,
                                             const float* __restrict__ key,
                                             float* __restrict__ dout) {
    extern __shared__ float smf[];
    const uint32_t sb = smem_u32(smf);
    const int t = threadIdx.x, wid = t >> 5, l = t & 31;
    const int b = blockIdx.y, d0 = blockIdx.x * 128;
    const float* keyb  = key + (long)b * N_ * D_;
    const float* attnb = g_attn + (long)b * K_ * C_;

    const int m0 = (wid & 1) * 32;    // slot offset
    const int n0 = (wid >> 1) * 32;   // d offset (0,32,64,96)

    const int laneA = ((((l >> 3) & 1) * 8 + (l & 7)) * 20) + (l >> 4) * 4;
    const int bK = l & 3, bN = l >> 2;   // B frag coords

    float c[2][4][4];
#pragma unroll
    for (int i = 0; i < 2; i++)
#pragma unroll
        for (int j = 0; j < 4; j++)
#pragma unroll
            for (int k = 0; k < 4; k++) c[i][j][k] = 0.f;

    auto issue = [&](int jc) {
        int s = jc % 3;
        uint32_t ab = sb + (s * SO_STG) * 4;
        uint32_t bb = ab + SO_ASZ * 4;
        {
            int row = t >> 2, f = t & 3;
            cp16(ab + (row * 20 + f * 4) * 4, attnb + (long)row * C_ + jc * 16 + f * 4);
        }
#pragma unroll
        for (int q = 0; q < 2; q++) {
            int idx = t + 256 * q, row = idx >> 5, dc = idx & 31;
            int cc = jc * 16 + row;
            const float* src = (cc < K_) ? (slot + (long)cc * D_ + d0 + dc * 4)
                                         : (keyb + (long)(cc - K_) * D_ + d0 + dc * 4);
            cp16(bb + (row * 136 + dc * 4) * 4, src);
        }
        cp_commit();
    };

    issue(0);
    issue(1);

    for (int jc = 0; jc < 68; jc++) {
        if (jc + 1 < 68) asm volatile("cp.async.wait_group 1;" ::: "memory");
        else             asm volatile("cp.async.wait_group 0;" ::: "memory");
        __syncthreads();
        if (jc + 2 < 68) issue(jc + 2);
        const int s = jc % 3;
        uint32_t a4 = sb + (s * SO_STG) * 4;
        const float* Bs = smf + s * SO_STG + SO_ASZ;
#pragma unroll
        for (int k8 = 0; k8 < 16; k8 += 8) {
            uint32_t a[2][4];
            ldsm4(a[0], a4 + ((m0)      * 20 + k8 + laneA) * 4);
            ldsm4(a[1], a4 + ((m0 + 16) * 20 + k8 + laneA) * 4);
#pragma unroll
            for (int p = 0; p < 4; p++) {
                int np = n0 + p * 8;
                uint32_t b2[2];
                b2[0] = __float_as_uint(Bs[(k8 + bK)     * 136 + np + bN]);
                b2[1] = __float_as_uint(Bs[(k8 + bK + 4) * 136 + np + bN]);
                mma8(c[0][p], a[0], b2);
                mma8(c[1][p], a[1], b2);
            }
        }
    }

    {
        int g = l >> 2, tq = l & 3;
#pragma unroll
        for (int mb = 0; mb < 2; mb++) {
            int s0 = m0 + 16 * mb + g, s1 = s0 + 8;
#pragma unroll
            for (int nb = 0; nb < 4; nb++) {
                int d = d0 + n0 + nb * 8 + 2 * tq;
                float2 w0 = {c[mb][nb][0], c[mb][nb][1]};
                float2 w1 = {c[mb][nb][2], c[mb][nb][3]};
                *(float2*)(dout + (long)b * K_ * D_ + (long)s0 * D_ + d) = w0;
                *(float2*)(dout + (long)b * K_ * D_ + (long)s1 * D_ + d) = w1;
            }
        }
    }
}

// ---------------------------------------------------------------------------
extern "C" void kernel_launch(void* const* d_in, const int* in_sizes, int n_in,
                              void* d_out, int out_size) {
    const float* key  = (const float*)d_in[0];
    const float* slot = (const float*)d_in[1];
    float* out = (float*)d_out;

    cudaFuncSetAttribute(k_dots, cudaFuncAttributeMaxDynamicSharedMemorySize, SD_TOT * 4);
    cudaFuncSetAttribute(k_out,  cudaFuncAttributeMaxDynamicSharedMemorySize, SO_TOT * 4);

    k_prep<<<K_, K_>>>(slot);
    k_dots<<<dim3(N_ / 256, B_), 256, SD_TOT * 4>>>(key, out);
    k_out<<<dim3(D_ / 128, B_), 256, SO_TOT * 4>>>(slot, key, out);
}

// round 14
// speedup vs baseline: 1.3586x; 1.3586x over previous
#include <cuda_runtime.h>
#include <cstdint>
#include <math.h>

constexpr int B_ = 64;
constexpr int N_ = 1024;
constexpr int D_ = 512;
constexpr int K_ = 64;
constexpr int C_ = K_ + N_;                      // 1088
constexpr long OUT_ELEMS = (long)B_ * K_ * D_;
constexpr long DOTS_OFF  = OUT_ELEMS;

#define TEMP_INV (1.0f / 0.07f)

__device__ float g_shat[K_ * D_];                // tf32-rounded normalized slots
__device__ float g_S[K_ * K_];                   // exact slot-slot cosines
__device__ float g_attn[(long)B_ * K_ * C_];     // tf32-rounded attn weights

__device__ __forceinline__ float to_tf32(float x) {
    asm("cvt.rna.tf32.f32 %0, %1;" : "=f"(x) : "f"(x));
    return x;
}
__device__ __forceinline__ uint32_t smem_u32(const void* p) {
    uint32_t a;
    asm("{ .reg .u64 t; cvta.to.shared.u64 t, %1; cvt.u32.u64 %0, t; }" : "=r"(a) : "l"(p));
    return a;
}
__device__ __forceinline__ void cp16(uint32_t dst, const void* src) {
    asm volatile("cp.async.cg.shared.global [%0], [%1], 16;" :: "r"(dst), "l"(src));
}
__device__ __forceinline__ void cp_commit() {
    asm volatile("cp.async.commit_group;" ::: "memory");
}
__device__ __forceinline__ void ldsm4(uint32_t* r, uint32_t addr) {
    asm volatile("ldmatrix.sync.aligned.m8n8.x4.shared.b16 {%0,%1,%2,%3}, [%4];"
        : "=r"(r[0]), "=r"(r[1]), "=r"(r[2]), "=r"(r[3]) : "r"(addr));
}
__device__ __forceinline__ void mma8(float* d, const uint32_t* a, const uint32_t* b) {
    asm volatile("mma.sync.aligned.m16n8k8.row.col.f32.tf32.tf32.f32 "
        "{%0,%1,%2,%3}, {%4,%5,%6,%7}, {%8,%9}, {%0,%1,%2,%3};"
        : "+f"(d[0]), "+f"(d[1]), "+f"(d[2]), "+f"(d[3])
        : "r"(a[0]), "r"(a[1]), "r"(a[2]), "r"(a[3]), "r"(b[0]), "r"(b[1]));
}

// ---------------------------------------------------------------------------
// K1: slot prep, parallel version. Block i (512 thr): thread (j = t>>3, p = t&7)
// computes 1/8th of dot(slot_i, slot_j) + 1/8th of ||slot_j||^2; oct-shfl
// reduce; S row + tf32 shat row.  (R13 found the old 64-thr version = 22 µs.)
// ---------------------------------------------------------------------------
__global__ __launch_bounds__(512) void k_prep(const float* __restrict__ slot) {
    const int i = blockIdx.x, t = threadIdx.x;
    const int j = t >> 3, p = t & 7;
    const float4* a = (const float4*)(slot + i * D_);
    const float4* b = (const float4*)(slot + j * D_);
    float dot = 0.f, nj = 0.f;
#pragma unroll
    for (int q = 0; q < 16; q++) {
        float4 x = a[p * 16 + q], y = b[p * 16 + q];
        dot += x.x * y.x + x.y * y.y + x.z * y.z + x.w * y.w;
        nj  += y.x * y.x + y.y * y.y + y.z * y.z + y.w * y.w;
    }
#pragma unroll
    for (int o = 1; o < 8; o <<= 1) {
        dot += __shfl_xor_sync(0xffffffffu, dot, o);
        nj  += __shfl_xor_sync(0xffffffffu, nj,  o);
    }
    __shared__ float n[64];
    if (p == 0) n[j] = nj;
    __syncthreads();
    float inv_i = 1.f / fmaxf(sqrtf(n[i]), 1e-12f);
    if (p == 0) {
        float inv_j = 1.f / fmaxf(sqrtf(nj), 1e-12f);
        g_S[i * K_ + j] = dot * inv_i * inv_j;
    }
    g_shat[i * D_ + t] = to_tf32(slot[i * D_ + t] * inv_i);
}

// ---------------------------------------------------------------------------
// K2: dots key-part via raw mma.sync + ldmatrix. CTA: 256 keys x 64 slots,
// 256 thr / 8 warps, warp tile 32(keys) x 64(slots). cp.async 3-stage, kc=16.
// Direct global epilogue. Fused key norms.  (proven R11/R12 core)
// ---------------------------------------------------------------------------
constexpr int SD_KINV = 0;                        // 256 floats
constexpr int SD_PIPE = 256;
constexpr int SD_ASZ  = 256 * 20;                 // A stage (floats)
constexpr int SD_BSZ  = 64 * 20;                  // B stage
constexpr int SD_STG  = SD_ASZ + SD_BSZ;          // 6400
constexpr int SD_TOT  = SD_PIPE + 3 * SD_STG;     // 19456 floats = 77824 B

__global__ __launch_bounds__(256, 2) void k_dots(const float* __restrict__ key,
                                                 float* __restrict__ dout) {
    extern __shared__ float smf[];
    const uint32_t sb = smem_u32(smf);
    const int t = threadIdx.x, wid = t >> 5, l = t & 31;
    const int b = blockIdx.y, n0blk = blockIdx.x * 256;
    const float* keyb = key + (long)b * N_ * D_;
    const int m0 = wid * 32;

    const int laneA = ((((l >> 3) & 1) * 8 + (l & 7)) * 20) + (l >> 4) * 4;
    const int laneB = (((l >> 4) * 8 + (l & 7)) * 20) + ((l >> 3) & 1) * 4;

    float c[2][8][4];
#pragma unroll
    for (int i = 0; i < 2; i++)
#pragma unroll
        for (int j = 0; j < 8; j++)
#pragma unroll
            for (int k = 0; k < 4; k++) c[i][j][k] = 0.f;

    float ss = 0.f;

    auto issue = [&](int jc) {
        int s = jc % 3;
        uint32_t ab = sb + (SD_PIPE + s * SD_STG) * 4;
        uint32_t bb = ab + SD_ASZ * 4;
        const float* gA = keyb + (long)n0blk * D_ + jc * 16;
#pragma unroll
        for (int q = 0; q < 4; q++) {
            int idx = t + 256 * q, row = idx >> 2, f = idx & 3;
            cp16(ab + (row * 20 + f * 4) * 4, gA + (long)row * D_ + f * 4);
        }
        {
            int row = t >> 2, f = t & 3;
            cp16(bb + (row * 20 + f * 4) * 4, g_shat + row * D_ + jc * 16 + f * 4);
        }
        cp_commit();
    };

    issue(0);
    issue(1);

    for (int jc = 0; jc < 32; jc++) {
        if (jc + 1 < 32) asm volatile("cp.async.wait_group 1;" ::: "memory");
        else             asm volatile("cp.async.wait_group 0;" ::: "memory");
        __syncthreads();
        if (jc + 2 < 32) issue(jc + 2);
        const int s = jc % 3;
        const float* As = smf + SD_PIPE + s * SD_STG;
        uint32_t a4 = sb + (SD_PIPE + s * SD_STG) * 4;
        uint32_t b4 = a4 + SD_ASZ * 4;
#pragma unroll
        for (int f = 0; f < 4; f++) {
            float4 v = *(const float4*)(As + t * 20 + f * 4);
            ss += v.x * v.x + v.y * v.y + v.z * v.z + v.w * v.w;
        }
#pragma unroll
        for (int k8 = 0; k8 < 16; k8 += 8) {
            uint32_t a[2][4], bf[4][4];
            ldsm4(a[0], a4 + ((m0)      * 20 + k8 + laneA) * 4);
            ldsm4(a[1], a4 + ((m0 + 16) * 20 + k8 + laneA) * 4);
#pragma unroll
            for (int p = 0; p < 4; p++)
                ldsm4(bf[p], b4 + ((16 * p) * 20 + k8 + laneB) * 4);
#pragma unroll
            for (int mb = 0; mb < 2; mb++)
#pragma unroll
                for (int p = 0; p < 4; p++) {
                    mma8(c[mb][2 * p],     a[mb], &bf[p][0]);
                    mma8(c[mb][2 * p + 1], a[mb], &bf[p][2]);
                }
        }
    }

    smf[SD_KINV + t] = 1.f / fmaxf(sqrtf(ss), 1e-12f);
    __syncthreads();

    {
        int g = l >> 2, tq = l & 3;
        float* base = dout + DOTS_OFF + (long)b * K_ * C_ + K_;
#pragma unroll
        for (int mb = 0; mb < 2; mb++) {
            int kl0 = m0 + 16 * mb + g, kl1 = kl0 + 8;
            float kv0 = smf[SD_KINV + kl0], kv1 = smf[SD_KINV + kl1];
            long key0 = n0blk + kl0, key1 = n0blk + kl1;
#pragma unroll
            for (int nb = 0; nb < 8; nb++) {
                int s0 = nb * 8 + 2 * tq;
                base[(long)s0 * C_ + key0]       = c[mb][nb][0] * kv0;
                base[(long)(s0 + 1) * C_ + key0] = c[mb][nb][1] * kv0;
                base[(long)s0 * C_ + key1]       = c[mb][nb][2] * kv1;
                base[(long)(s0 + 1) * C_ + key1] = c[mb][nb][3] * kv1;
            }
        }
    }
}

// ---------------------------------------------------------------------------
// K3: row softmax with block-causal mask -> g_attn (tf32-rounded);
// slot-slot dots -> output.  (proven standalone version)
// ---------------------------------------------------------------------------
__global__ __launch_bounds__(256) void k_softmax(float* __restrict__ dout) {
    int row  = (blockIdx.x * blockDim.x + threadIdx.x) >> 5;
    int lane = threadIdx.x & 31;
    int b = row >> 6, i = row & 63;

    float* drow = dout + DOTS_OFF + (long)b * K_ * C_ + (long)i * C_;

    float sv[2], kvv[32];
    float m = -1e30f;
#pragma unroll
    for (int r = 0; r < 2; r++) {
        int c = lane + r * 32;
        float s = g_S[i * K_ + c];
        sv[r] = s;
        drow[c] = s;
        if (c < i) m = fmaxf(m, s);
    }
#pragma unroll
    for (int r = 0; r < 32; r++) {
        float v = drow[K_ + lane + r * 32];
        kvv[r] = v;
        m = fmaxf(m, v);
    }
#pragma unroll
    for (int o = 16; o; o >>= 1) m = fmaxf(m, __shfl_xor_sync(0xffffffffu, m, o));

    float sum = 0.f, es[2], ek[32];
#pragma unroll
    for (int r = 0; r < 2; r++) {
        int c = lane + r * 32;
        float x = (c < i) ? __expf((sv[r] - m) * TEMP_INV) : 0.f;
        es[r] = x; sum += x;
    }
#pragma unroll
    for (int r = 0; r < 32; r++) {
        float x = __expf((kvv[r] - m) * TEMP_INV);
        ek[r] = x; sum += x;
    }
#pragma unroll
    for (int o = 16; o; o >>= 1) sum += __shfl_xor_sync(0xffffffffu, sum, o);

    float inv = 1.f / (sum * (1.f + 1e-7f));
    float* at = g_attn + (long)row * C_;
#pragma unroll
    for (int r = 0; r < 2; r++) at[lane + r * 32] = to_tf32(es[r] * inv);
#pragma unroll
    for (int r = 0; r < 32; r++) at[K_ + lane + r * 32] = to_tf32(ek[r] * inv);
}

// ---------------------------------------------------------------------------
// K4: out = attn_n @ [slots; key_b].  (proven R12 core)
// ---------------------------------------------------------------------------
constexpr int SO_ASZ = 64 * 20;                   // 1280 floats per stage
constexpr int SO_BSZ = 16 * 136;                  // 2176
constexpr int SO_STG = SO_ASZ + SO_BSZ;           // 3456
constexpr int SO_TOT = 3 * SO_STG;                // 10368 floats = 41472 B

__global__ __launch_bounds__(256) void k_out(const float* __restrict__ slot,
                                             const float* __restrict__ key,
                                             float* __restrict__ dout) {
    extern __shared__ float smf[];
    const uint32_t sb = smem_u32(smf);
    const int t = threadIdx.x, wid = t >> 5, l = t & 31;
    const int b = blockIdx.y, d0 = blockIdx.x * 128;
    const float* keyb  = key + (long)b * N_ * D_;
    const float* attnb = g_attn + (long)b * K_ * C_;

    const int m0 = (wid & 1) * 32;    // slot offset
    const int n0 = (wid >> 1) * 32;   // d offset (0,32,64,96)

    const int laneA = ((((l >> 3) & 1) * 8 + (l & 7)) * 20) + (l >> 4) * 4;
    const int bK = l & 3, bN = l >> 2;   // B frag coords

    float c[2][4][4];
#pragma unroll
    for (int i = 0; i < 2; i++)
#pragma unroll
        for (int j = 0; j < 4; j++)
#pragma unroll
            for (int k = 0; k < 4; k++) c[i][j][k] = 0.f;

    auto issue = [&](int jc) {
        int s = jc % 3;
        uint32_t ab = sb + (s * SO_STG) * 4;
        uint32_t bb = ab + SO_ASZ * 4;
        {
            int row = t >> 2, f = t & 3;
            cp16(ab + (row * 20 + f * 4) * 4, attnb + (long)row * C_ + jc * 16 + f * 4);
        }
#pragma unroll
        for (int q = 0; q < 2; q++) {
            int idx = t + 256 * q, row = idx >> 5, dc = idx & 31;
            int cc = jc * 16 + row;
            const float* src = (cc < K_) ? (slot + (long)cc * D_ + d0 + dc * 4)
                                         : (keyb + (long)(cc - K_) * D_ + d0 + dc * 4);
            cp16(bb + (row * 136 + dc * 4) * 4, src);
        }
        cp_commit();
    };

    issue(0);
    issue(1);

    for (int jc = 0; jc < 68; jc++) {
        if (jc + 1 < 68) asm volatile("cp.async.wait_group 1;" ::: "memory");
        else             asm volatile("cp.async.wait_group 0;" ::: "memory");
        __syncthreads();
        if (jc + 2 < 68) issue(jc + 2);
        const int s = jc % 3;
        uint32_t a4 = sb + (s * SO_STG) * 4;
        const float* Bs = smf + s * SO_STG + SO_ASZ;
#pragma unroll
        for (int k8 = 0; k8 < 16; k8 += 8) {
            uint32_t a[2][4];
            ldsm4(a[0], a4 + ((m0)      * 20 + k8 + laneA) * 4);
            ldsm4(a[1], a4 + ((m0 + 16) * 20 + k8 + laneA) * 4);
#pragma unroll
            for (int p = 0; p < 4; p++) {
                int np = n0 + p * 8;
                uint32_t b2[2];
                b2[0] = __float_as_uint(Bs[(k8 + bK)     * 136 + np + bN]);
                b2[1] = __float_as_uint(Bs[(k8 + bK + 4) * 136 + np + bN]);
                mma8(c[0][p], a[0], b2);
                mma8(c[1][p], a[1], b2);
            }
        }
    }

    {
        int g = l >> 2, tq = l & 3;
#pragma unroll
        for (int mb = 0; mb < 2; mb++) {
            int s0 = m0 + 16 * mb + g, s1 = s0 + 8;
#pragma unroll
            for (int nb = 0; nb < 4; nb++) {
                int d = d0 + n0 + nb * 8 + 2 * tq;
                float2 w0 = {c[mb][nb][0], c[mb][nb][1]};
                float2 w1 = {c[mb][nb][2], c[mb][nb][3]};
                *(float2*)(dout + (long)b * K_ * D_ + (long)s0 * D_ + d) = w0;
                *(float2*)(dout + (long)b * K_ * D_ + (long)s1 * D_ + d) = w1;
            }
        }
    }
}

// ---------------------------------------------------------------------------
extern "C" void kernel_launch(void* const* d_in, const int* in_sizes, int n_in,
                              void* d_out, int out_size) {
    const float* key  = (const float*)d_in[0];
    const float* slot = (const float*)d_in[1];
    float* out = (float*)d_out;

    cudaFuncSetAttribute(k_dots, cudaFuncAttributeMaxDynamicSharedMemorySize, SD_TOT * 4);
    cudaFuncSetAttribute(k_out,  cudaFuncAttributeMaxDynamicSharedMemorySize, SO_TOT * 4);

    k_prep<<<K_, 512>>>(slot);
    k_dots<<<dim3(N_ / 256, B_), 256, SD_TOT * 4>>>(key, out);
    k_softmax<<<(B_ * K_) / 8, 256>>>(out);
    k_out<<<dim3(D_ / 128, B_), 256, SO_TOT * 4>>>(slot, key, out);   // 4th: ncu target
}